// round 4
// baseline (speedup 1.0000x reference)
#include <cuda_runtime.h>

#define H       64
#define NSEG    1024
#define LPB     256      // lanes per block == threads
#define NWARP   (LPB / 32)
#define PCOLS   192      // pooling feature columns

// ---------------- scratch (no allocations allowed) ----------------
__device__ float g_seg_sum[NSEG + 1];  // +1 = dump slot for out-of-range lanes

// ---------------- kernel 0: init ----------------
__global__ void init_kernel(float* __restrict__ out, int out_size) {
    int i = blockIdx.x * blockDim.x + threadIdx.x;
    if (i < out_size) out[i] = 0.0f;
    if (i <= NSEG) g_seg_sum[i] = 0.0f;
}

// ---------------- kernel 1: fused score + exp + seg-sum + unnormalized pool --
__global__ __launch_bounds__(LPB) void fused_kernel(
    const float* __restrict__ ht, const float* __restrict__ info,
    const float* __restrict__ fut, const int* __restrict__ seg,
    const float* __restrict__ w1, const float* __restrict__ b1,
    const float* __restrict__ w2, const float* __restrict__ b2,
    float* __restrict__ out, int M)
{
    __shared__ __align__(16) float w1s[128 * 16];
    __shared__ __align__(16) float b1s[16];
    __shared__ __align__(16) float w2s[16];
    __shared__ float b2s;
    __shared__ float ex_s[LPB];
    __shared__ int   seg_s[LPB];
    __shared__ int   run_start[LPB + 1];
    __shared__ int   warp_cnt[NWARP];
    __shared__ int   nruns_s;

    const int tid = threadIdx.x;
    const int base = blockIdx.x * LPB;
    int nl = M - base;
    if (nl > LPB) nl = LPB;

    // ---- load MLP weights ----
    for (int i = tid; i < 128 * 16; i += LPB) w1s[i] = w1[i];
    if (tid < 16) { b1s[tid] = b1[tid]; w2s[tid] = w2[tid]; }
    if (tid == 0) b2s = b2[0];
    __syncthreads();

    // ---- phase 1: per-lane MLP, packed f32x2 accumulators, direct row loads
    const int lane = base + tid;
    float ex = 0.0f;
    int   s  = NSEG;                 // dump slot for OOB lanes
    if (tid < nl) {
        unsigned long long hp[8];    // hp[q] = hidden units (2q, 2q+1)
#pragma unroll
        for (int q = 0; q < 8; q++)
            hp[q] = reinterpret_cast<const unsigned long long*>(b1s)[q];

#pragma unroll
        for (int half = 0; half < 2; half++) {
            const float4* x4 = reinterpret_cast<const float4*>(half ? info : ht)
                             + (size_t)lane * (H / 4);
#pragma unroll
            for (int kk = 0; kk < H / 4; kk++) {
                float4 xv = x4[kk];
                const int kbase = half * H + kk * 4;
#pragma unroll
                for (int c = 0; c < 4; c++) {
                    float x = (&xv.x)[c];
                    unsigned long long xx;
                    asm("mov.b64 %0, {%1, %1};" : "=l"(xx) : "f"(x));
                    const unsigned long long* wr =
                        reinterpret_cast<const unsigned long long*>(&w1s[(kbase + c) * 16]);
#pragma unroll
                    for (int q = 0; q < 8; q++)
                        asm("fma.rn.f32x2 %0, %1, %2, %0;"
                            : "+l"(hp[q]) : "l"(xx), "l"(wr[q]));
                }
            }
        }

        float sc = b2s;
#pragma unroll
        for (int q = 0; q < 8; q++) {
            float lo, hi;
            asm("mov.b64 {%0, %1}, %2;" : "=f"(lo), "=f"(hi) : "l"(hp[q]));
            sc = fmaf(fmaxf(lo, 0.0f), w2s[2 * q + 0], sc);
            sc = fmaf(fmaxf(hi, 0.0f), w2s[2 * q + 1], sc);
        }
        s  = seg[lane];
        ex = __expf(sc);             // scores ~|2|: no max-shift needed
        seg_s[tid] = s;
    }
    ex_s[tid] = ex;

    // ---- per-segment sum of ex (sorted ids -> warp-segmented reduce) ----
    {
        const int li = tid & 31;
        float v = ex;
#pragma unroll
        for (int o = 1; o < 32; o <<= 1) {
            float u  = __shfl_down_sync(0xffffffffu, v, o);
            int   s2 = __shfl_down_sync(0xffffffffu, s, o);
            if (li + o < 32 && s2 == s) v += u;
        }
        int sp = __shfl_up_sync(0xffffffffu, s, 1);
        if ((li == 0 || sp != s) && v != 0.0f)
            atomicAdd(&g_seg_sum[s], v);
    }
    __syncthreads();

    // ---- build ordered run boundaries over [0, nl) ----
    int flag = 0;
    if (tid < nl) flag = (tid == 0) || (seg_s[tid] != seg_s[tid - 1]);
    unsigned m = __ballot_sync(0xffffffffu, flag);
    const int wid = tid >> 5, li = tid & 31;
    if (li == 0) warp_cnt[wid] = __popc(m);
    __syncthreads();
    if (tid == 0) {
        int tot = 0;
#pragma unroll
        for (int w = 0; w < NWARP; w++) { int c = warp_cnt[w]; warp_cnt[w] = tot; tot += c; }
        nruns_s = tot;
        run_start[tot] = nl;
    }
    __syncthreads();
    if (flag)
        run_start[warp_cnt[wid] + __popc(m & ((1u << li) - 1u))] = tid;
    __syncthreads();

    // ---- phase 2: unnormalized pooling, one feature column per thread ----
    if (tid < PCOLS) {
        const float* src2;
        if (tid < 64)       src2 = ht   + tid;
        else if (tid < 128) src2 = info + (tid - 64);
        else                src2 = fut  + (tid - 128);
        src2 += (size_t)base * H;

        const int nruns = nruns_s;
        for (int r = 0; r < nruns; r++) {
            const int st = run_start[r];
            const int en = run_start[r + 1];
            const int sr = seg_s[st];
            float a0 = 0.f, a1 = 0.f, a2 = 0.f, a3 = 0.f;
            int i = st;
            for (; i + 4 <= en; i += 4) {
                a0 = fmaf(ex_s[i    ], src2[(size_t)(i    ) * H], a0);
                a1 = fmaf(ex_s[i + 1], src2[(size_t)(i + 1) * H], a1);
                a2 = fmaf(ex_s[i + 2], src2[(size_t)(i + 2) * H], a2);
                a3 = fmaf(ex_s[i + 3], src2[(size_t)(i + 3) * H], a3);
            }
            for (; i < en; i++)
                a0 = fmaf(ex_s[i], src2[(size_t)i * H], a0);
            float acc = (a0 + a1) + (a2 + a3);
            atomicAdd(&out[sr * PCOLS + tid], acc);
        }
    }
}

// ---------------- kernel 2: normalize out by seg_sum ----------------
__global__ void normalize_kernel(float* __restrict__ out) {
    int i = blockIdx.x * blockDim.x + threadIdx.x;   // i < NSEG*192
    if (i < NSEG * PCOLS)
        out[i] /= g_seg_sum[i / PCOLS];
}

// ---------------- launch ----------------
extern "C" void kernel_launch(void* const* d_in, const int* in_sizes, int n_in,
                              void* d_out, int out_size)
{
    const float* ht   = (const float*)d_in[0];
    const float* info = (const float*)d_in[1];
    const float* fut  = (const float*)d_in[2];
    const int*   seg  = (const int*)  d_in[3];
    const float* w1   = (const float*)d_in[4];
    const float* b1   = (const float*)d_in[5];
    const float* w2   = (const float*)d_in[6];
    const float* b2   = (const float*)d_in[7];
    float* out = (float*)d_out;

    int M = in_sizes[0] / H;

    int init_n = out_size > (NSEG + 1) ? out_size : (NSEG + 1);
    init_kernel<<<(init_n + 255) / 256, 256>>>(out, out_size);

    fused_kernel<<<(M + LPB - 1) / LPB, LPB>>>(ht, info, fut, seg,
                                               w1, b1, w2, b2, out, M);

    normalize_kernel<<<(NSEG * PCOLS + 255) / 256, 256>>>(out);
}

// round 5
// speedup vs baseline: 1.1701x; 1.1701x over previous
#include <cuda_runtime.h>

#define H       64
#define NSEG    1024
#define MMAX    400000
#define PCOLS   192

#define SBLK    256      // score kernel threads (== lanes/block)
#define PLANES  512      // pool kernel lanes per block
#define PTHR    256      // pool kernel threads
#define NCHUNK  (PLANES / 32)

// ---------------- scratch (no allocations allowed) ----------------
__device__ float g_scores[MMAX];       // ex = exp(score), unnormalized
__device__ float g_seg_sum[NSEG + 1];  // +1 = dump slot

// ---------------- kernel 0: init ----------------
__global__ void init_kernel(float* __restrict__ out, int out_size) {
    int i = blockIdx.x * blockDim.x + threadIdx.x;
    if (i < out_size) out[i] = 0.0f;
    if (i <= NSEG) g_seg_sum[i] = 0.0f;
}

// ---------------- kernel 1: MLP score -> ex, per-segment sum ----------------
__global__ __launch_bounds__(SBLK) void score_kernel(
    const float* __restrict__ ht, const float* __restrict__ info,
    const int* __restrict__ seg,
    const float* __restrict__ w1, const float* __restrict__ b1,
    const float* __restrict__ w2, const float* __restrict__ b2, int M)
{
    __shared__ __align__(16) float w1s[128 * 16];
    __shared__ float b1s[16], w2s[16];
    __shared__ float b2s;

    const int tid = threadIdx.x;
    for (int i = tid; i < 128 * 16; i += SBLK) w1s[i] = w1[i];
    if (tid < 16) { b1s[tid] = b1[tid]; w2s[tid] = w2[tid]; }
    if (tid == 0) b2s = b2[0];
    __syncthreads();

    const int lane = blockIdx.x * SBLK + tid;

    float ex = 0.0f;
    int   s  = NSEG;
    if (lane < M) {
        float h[16];
#pragma unroll
        for (int j = 0; j < 16; j++) h[j] = b1s[j];

#pragma unroll
        for (int half = 0; half < 2; half++) {
            const float4* x4 = reinterpret_cast<const float4*>(half ? info : ht)
                             + (size_t)lane * (H / 4);
#pragma unroll
            for (int kk = 0; kk < H / 4; kk++) {
                float4 xv = x4[kk];
                const int kbase = half * H + kk * 4;
#pragma unroll
                for (int c = 0; c < 4; c++) {
                    float x = (&xv.x)[c];
                    const float4* wr = reinterpret_cast<const float4*>(&w1s[(kbase + c) * 16]);
#pragma unroll
                    for (int q = 0; q < 4; q++) {
                        float4 w = wr[q];
                        h[q * 4 + 0] = fmaf(x, w.x, h[q * 4 + 0]);
                        h[q * 4 + 1] = fmaf(x, w.y, h[q * 4 + 1]);
                        h[q * 4 + 2] = fmaf(x, w.z, h[q * 4 + 2]);
                        h[q * 4 + 3] = fmaf(x, w.w, h[q * 4 + 3]);
                    }
                }
            }
        }
        float sc = b2s;
#pragma unroll
        for (int j = 0; j < 16; j++) sc = fmaf(fmaxf(h[j], 0.0f), w2s[j], sc);

        s  = seg[lane];
        ex = __expf(sc);             // scores tiny (~|2|): no max-shift needed
        g_scores[lane] = ex;
    }

    // warp-segmented reduce (segment ids sorted -> contiguous runs)
    const int li = tid & 31;
    float v = ex;
#pragma unroll
    for (int o = 1; o < 32; o <<= 1) {
        float u  = __shfl_down_sync(0xffffffffu, v, o);
        int   s2 = __shfl_down_sync(0xffffffffu, s, o);
        if (li + o < 32 && s2 == s) v += u;
    }
    int sp = __shfl_up_sync(0xffffffffu, s, 1);
    if ((li == 0 || sp != s) && v != 0.0f)
        atomicAdd(&g_seg_sum[s], v);
}

// ---------------- kernel 2: weighted pooling (normalized probs) -------------
__global__ __launch_bounds__(PTHR) void pool_kernel(
    const float* __restrict__ ht, const float* __restrict__ info,
    const float* __restrict__ fut, const int* __restrict__ seg,
    float* __restrict__ out, int M)
{
    __shared__ float    prob_s[PLANES];
    __shared__ int      seg_s[PLANES];
    __shared__ int      run_start[PLANES + 1];
    __shared__ unsigned cmask[NCHUNK];
    __shared__ int      ccnt[NCHUNK];
    __shared__ int      nruns_s;

    const int tid = threadIdx.x;
    const int base = blockIdx.x * PLANES;
    int nl = M - base;
    if (nl > PLANES) nl = PLANES;

    for (int i = tid; i < nl; i += PTHR) {
        int s = seg[base + i];
        seg_s[i] = s;
        prob_s[i] = g_scores[base + i] / g_seg_sum[s];
    }
    __syncthreads();

    // ---- ordered run boundaries over [0, nl) via per-warp ballot ----
#pragma unroll
    for (int k = 0; k < PLANES / PTHR; k++) {
        int i = k * PTHR + tid;
        int flag = (i < nl) && (i == 0 || seg_s[i] != seg_s[i - 1]);
        unsigned m = __ballot_sync(0xffffffffu, flag);
        if ((tid & 31) == 0) {
            int chunk = k * (PTHR / 32) + (tid >> 5);
            cmask[chunk] = m;
            ccnt[chunk] = __popc(m);
        }
    }
    __syncthreads();
    if (tid == 0) {
        int tot = 0;
#pragma unroll
        for (int c = 0; c < NCHUNK; c++) { int n = ccnt[c]; ccnt[c] = tot; tot += n; }
        nruns_s = tot;
        run_start[tot] = nl;
    }
    __syncthreads();
#pragma unroll
    for (int k = 0; k < PLANES / PTHR; k++) {
        int i = k * PTHR + tid;
        int flag = (i < nl) && (i == 0 || seg_s[i] != seg_s[i - 1]);
        if (flag) {
            int chunk = k * (PTHR / 32) + (tid >> 5);
            run_start[ccnt[chunk] + __popc(cmask[chunk] & ((1u << (tid & 31)) - 1u))] = i;
        }
    }
    __syncthreads();

    // ---- column-per-thread accumulation with 8-deep load batches ----
    if (tid < PCOLS) {
        const float* src;
        if (tid < 64)       src = ht   + tid;
        else if (tid < 128) src = info + (tid - 64);
        else                src = fut  + (tid - 128);
        src += (size_t)base * H;

        const int nruns = nruns_s;
        for (int r = 0; r < nruns; r++) {
            const int st = run_start[r];
            const int en = run_start[r + 1];
            const int sr = seg_s[st];
            float a0 = 0.f, a1 = 0.f, a2 = 0.f, a3 = 0.f;
            float a4 = 0.f, a5 = 0.f, a6 = 0.f, a7 = 0.f;
            int i = st;
            for (; i + 8 <= en; i += 8) {
                float x0 = src[(size_t)(i + 0) * H];
                float x1 = src[(size_t)(i + 1) * H];
                float x2 = src[(size_t)(i + 2) * H];
                float x3 = src[(size_t)(i + 3) * H];
                float x4 = src[(size_t)(i + 4) * H];
                float x5 = src[(size_t)(i + 5) * H];
                float x6 = src[(size_t)(i + 6) * H];
                float x7 = src[(size_t)(i + 7) * H];
                a0 = fmaf(prob_s[i + 0], x0, a0);
                a1 = fmaf(prob_s[i + 1], x1, a1);
                a2 = fmaf(prob_s[i + 2], x2, a2);
                a3 = fmaf(prob_s[i + 3], x3, a3);
                a4 = fmaf(prob_s[i + 4], x4, a4);
                a5 = fmaf(prob_s[i + 5], x5, a5);
                a6 = fmaf(prob_s[i + 6], x6, a6);
                a7 = fmaf(prob_s[i + 7], x7, a7);
            }
            for (; i < en; i++)
                a0 = fmaf(prob_s[i], src[(size_t)i * H], a0);
            float acc = ((a0 + a1) + (a2 + a3)) + ((a4 + a5) + (a6 + a7));
            atomicAdd(&out[sr * PCOLS + tid], acc);
        }
    }
}

// ---------------- launch ----------------
extern "C" void kernel_launch(void* const* d_in, const int* in_sizes, int n_in,
                              void* d_out, int out_size)
{
    const float* ht   = (const float*)d_in[0];
    const float* info = (const float*)d_in[1];
    const float* fut  = (const float*)d_in[2];
    const int*   seg  = (const int*)  d_in[3];
    const float* w1   = (const float*)d_in[4];
    const float* b1   = (const float*)d_in[5];
    const float* w2   = (const float*)d_in[6];
    const float* b2   = (const float*)d_in[7];
    float* out = (float*)d_out;

    int M = in_sizes[0] / H;

    int init_n = out_size > (NSEG + 1) ? out_size : (NSEG + 1);
    init_kernel<<<(init_n + 255) / 256, 256>>>(out, out_size);

    score_kernel<<<(M + SBLK - 1) / SBLK, SBLK>>>(ht, info, seg, w1, b1, w2, b2, M);

    pool_kernel<<<(M + PLANES - 1) / PLANES, PTHR>>>(ht, info, fut, seg, out, M);
}

// round 6
// speedup vs baseline: 1.1985x; 1.0243x over previous
#include <cuda_runtime.h>

#define H       64
#define NSEG    1024
#define MMAX    400000
#define PCOLS   192

#define SBLK    256      // score kernel threads (== lanes/block)
#define PLANES  512      // pool kernel lanes per block
#define PTHR    288      // pool threads: 96 col-pair slots x 3 lane-groups
#define NCHUNK  (PLANES / 32)

// ---------------- scratch (no allocations allowed) ----------------
__device__ float g_scores[MMAX];       // ex = exp(score), unnormalized
__device__ float g_seg_sum[NSEG + 1];  // +1 = dump slot

// ---------------- kernel 0: init ----------------
__global__ void init_kernel(float* __restrict__ out, int out_size) {
    int i = blockIdx.x * blockDim.x + threadIdx.x;
    if (i < out_size) out[i] = 0.0f;
    if (i <= NSEG) g_seg_sum[i] = 0.0f;
}

// ---------------- kernel 1: MLP score -> ex, per-segment sum ----------------
__global__ __launch_bounds__(SBLK) void score_kernel(
    const float* __restrict__ ht, const float* __restrict__ info,
    const int* __restrict__ seg,
    const float* __restrict__ w1, const float* __restrict__ b1,
    const float* __restrict__ w2, const float* __restrict__ b2, int M)
{
    __shared__ __align__(16) float w1s[128 * 16];
    __shared__ __align__(16) float b1s[16];
    __shared__ __align__(16) float w2s[16];
    __shared__ float b2s;

    const int tid = threadIdx.x;
    for (int i = tid; i < 128 * 16; i += SBLK) w1s[i] = w1[i];
    if (tid < 16) { b1s[tid] = b1[tid]; w2s[tid] = w2[tid]; }
    if (tid == 0) b2s = b2[0];
    __syncthreads();

    const int lane = blockIdx.x * SBLK + tid;

    float ex = 0.0f;
    int   s  = NSEG;
    if (lane < M) {
        // hp[q] holds hidden units (2q, 2q+1) as packed f32x2
        unsigned long long hp[8];
#pragma unroll
        for (int q = 0; q < 8; q++)
            hp[q] = reinterpret_cast<const unsigned long long*>(b1s)[q];

#pragma unroll
        for (int half = 0; half < 2; half++) {
            const float4* x4 = reinterpret_cast<const float4*>(half ? info : ht)
                             + (size_t)lane * (H / 4);
#pragma unroll
            for (int kk = 0; kk < H / 4; kk++) {
                float4 xv = x4[kk];
                const int kbase = half * H + kk * 4;
#pragma unroll
                for (int c = 0; c < 4; c++) {
                    float x = (&xv.x)[c];
                    unsigned long long xx;
                    asm("mov.b64 %0, {%1, %1};" : "=l"(xx) : "f"(x));
                    const unsigned long long* wr =
                        reinterpret_cast<const unsigned long long*>(&w1s[(kbase + c) * 16]);
#pragma unroll
                    for (int q = 0; q < 8; q++)
                        asm("fma.rn.f32x2 %0, %1, %2, %0;"
                            : "+l"(hp[q]) : "l"(xx), "l"(wr[q]));
                }
            }
        }

        float sc = b2s;
#pragma unroll
        for (int q = 0; q < 8; q++) {
            float lo, hi;
            asm("mov.b64 {%0, %1}, %2;" : "=f"(lo), "=f"(hi) : "l"(hp[q]));
            sc = fmaf(fmaxf(lo, 0.0f), w2s[2 * q + 0], sc);
            sc = fmaf(fmaxf(hi, 0.0f), w2s[2 * q + 1], sc);
        }
        s  = seg[lane];
        ex = __expf(sc);             // scores tiny (~|2|): no max-shift needed
        g_scores[lane] = ex;
    }

    // warp-segmented reduce (segment ids sorted -> contiguous runs)
    const int li = tid & 31;
    float v = ex;
#pragma unroll
    for (int o = 1; o < 32; o <<= 1) {
        float u  = __shfl_down_sync(0xffffffffu, v, o);
        int   s2 = __shfl_down_sync(0xffffffffu, s, o);
        if (li + o < 32 && s2 == s) v += u;
    }
    int sp = __shfl_up_sync(0xffffffffu, s, 1);
    if ((li == 0 || sp != s) && v != 0.0f)
        atomicAdd(&g_seg_sum[s], v);
}

// ---------------- kernel 2: weighted pooling (normalized probs) -------------
// 288 threads: slot = tid%96 -> (array, column-pair), group = tid/96 strides
// run lanes by 3. Every warp-request covers a full 256B row (float2 loads).
__global__ __launch_bounds__(PTHR) void pool_kernel(
    const float* __restrict__ ht, const float* __restrict__ info,
    const float* __restrict__ fut, const int* __restrict__ seg,
    float* __restrict__ out, int M)
{
    __shared__ float    prob_s[PLANES];
    __shared__ int      seg_s[PLANES];
    __shared__ int      run_start[PLANES + 1];
    __shared__ unsigned cmask[NCHUNK];
    __shared__ int      ccnt[NCHUNK];
    __shared__ int      nruns_s;

    const int tid = threadIdx.x;
    const int base = blockIdx.x * PLANES;
    int nl = M - base;
    if (nl > PLANES) nl = PLANES;

    for (int i = tid; i < nl; i += PTHR) {
        int s = seg[base + i];
        seg_s[i] = s;
        prob_s[i] = g_scores[base + i] / g_seg_sum[s];
    }
    __syncthreads();

    // ---- ordered run boundaries over [0, nl) via per-warp ballot ----
    // 2 passes of 288 threads cover 576 >= PLANES indices (32-aligned per warp)
#pragma unroll
    for (int k = 0; k < 2; k++) {
        int i = k * PTHR + tid;
        int flag = (i < nl) && (i == 0 || (i < PLANES && seg_s[i] != seg_s[i - 1]));
        unsigned m = __ballot_sync(0xffffffffu, flag);
        int chunk = i >> 5;
        if ((tid & 31) == 0 && chunk < NCHUNK) {
            cmask[chunk] = m;
            ccnt[chunk] = __popc(m);
        }
    }
    __syncthreads();
    if (tid == 0) {
        int tot = 0;
#pragma unroll
        for (int c = 0; c < NCHUNK; c++) { int n = ccnt[c]; ccnt[c] = tot; tot += n; }
        nruns_s = tot;
        run_start[tot] = nl;
    }
    __syncthreads();
#pragma unroll
    for (int k = 0; k < 2; k++) {
        int i = k * PTHR + tid;
        int flag = (i < nl) && (i == 0 || (i < PLANES && seg_s[i] != seg_s[i - 1]));
        if (flag) {
            int chunk = i >> 5;
            run_start[ccnt[chunk] + __popc(cmask[chunk] & ((1u << (i & 31)) - 1u))] = i;
        }
    }
    __syncthreads();

    // ---- accumulation: float2 column pairs, 3-way lane-group striding ----
    const int g     = tid / 96;        // lane-group 0..2
    const int slot  = tid % 96;
    const int arr   = slot >> 5;       // 0:ht 1:info 2:fut
    const int pairc = slot & 31;       // column pair within array
    const float* srcb = (arr == 0) ? ht : (arr == 1) ? info : fut;
    const float* src  = srcb + (size_t)base * H + pairc * 2;
    const int ocol = arr * 64 + pairc * 2;

    const int nruns = nruns_s;
    for (int r = 0; r < nruns; r++) {
        const int st = run_start[r];
        const int en = run_start[r + 1];
        const int sr = seg_s[st];
        float ax0 = 0.f, ay0 = 0.f, ax1 = 0.f, ay1 = 0.f;
        float ax2 = 0.f, ay2 = 0.f, ax3 = 0.f, ay3 = 0.f;
        int i = st + g;
        for (; i + 9 < en; i += 12) {
            float2 v0 = *reinterpret_cast<const float2*>(src + (size_t)(i    ) * H);
            float2 v1 = *reinterpret_cast<const float2*>(src + (size_t)(i + 3) * H);
            float2 v2 = *reinterpret_cast<const float2*>(src + (size_t)(i + 6) * H);
            float2 v3 = *reinterpret_cast<const float2*>(src + (size_t)(i + 9) * H);
            float p0 = prob_s[i], p1 = prob_s[i + 3], p2 = prob_s[i + 6], p3 = prob_s[i + 9];
            ax0 = fmaf(p0, v0.x, ax0); ay0 = fmaf(p0, v0.y, ay0);
            ax1 = fmaf(p1, v1.x, ax1); ay1 = fmaf(p1, v1.y, ay1);
            ax2 = fmaf(p2, v2.x, ax2); ay2 = fmaf(p2, v2.y, ay2);
            ax3 = fmaf(p3, v3.x, ax3); ay3 = fmaf(p3, v3.y, ay3);
        }
        for (; i < en; i += 3) {
            float2 v = *reinterpret_cast<const float2*>(src + (size_t)i * H);
            float p = prob_s[i];
            ax0 = fmaf(p, v.x, ax0); ay0 = fmaf(p, v.y, ay0);
        }
        float ax = (ax0 + ax1) + (ax2 + ax3);
        float ay = (ay0 + ay1) + (ay2 + ay3);
        if (ax != 0.f || ay != 0.f || true) {
            atomicAdd(&out[sr * PCOLS + ocol    ], ax);
            atomicAdd(&out[sr * PCOLS + ocol + 1], ay);
        }
    }
}

// ---------------- launch ----------------
extern "C" void kernel_launch(void* const* d_in, const int* in_sizes, int n_in,
                              void* d_out, int out_size)
{
    const float* ht   = (const float*)d_in[0];
    const float* info = (const float*)d_in[1];
    const float* fut  = (const float*)d_in[2];
    const int*   seg  = (const int*)  d_in[3];
    const float* w1   = (const float*)d_in[4];
    const float* b1   = (const float*)d_in[5];
    const float* w2   = (const float*)d_in[6];
    const float* b2   = (const float*)d_in[7];
    float* out = (float*)d_out;

    int M = in_sizes[0] / H;

    int init_n = out_size > (NSEG + 1) ? out_size : (NSEG + 1);
    init_kernel<<<(init_n + 255) / 256, 256>>>(out, out_size);

    score_kernel<<<(M + SBLK - 1) / SBLK, SBLK>>>(ht, info, seg, w1, b1, w2, b2, M);

    pool_kernel<<<(M + PLANES - 1) / PLANES, PTHR>>>(ht, info, fut, seg, out, M);
}

// round 7
// speedup vs baseline: 1.4238x; 1.1880x over previous
#include <cuda_runtime.h>

#define H       64
#define NSEG    1024
#define LPB     256      // lanes per block == threads
#define PCOLS   192
#define FULLM   0xffffffffu

// ---------------- scratch (no allocations allowed) ----------------
__device__ float g_seg_sum[NSEG];

// ---------------- kernel 0: init ----------------
__global__ void init_kernel(float* __restrict__ out, int out_size) {
    int i = blockIdx.x * blockDim.x + threadIdx.x;
    if (i < out_size) out[i] = 0.0f;
    if (i < NSEG) g_seg_sum[i] = 0.0f;
}

// ---------------- kernel 1: MLP + exp + seg-sum + warp-local pooling --------
__global__ __launch_bounds__(LPB) void mega_kernel(
    const float* __restrict__ ht, const float* __restrict__ info,
    const float* __restrict__ fut, const int* __restrict__ seg,
    const float* __restrict__ w1, const float* __restrict__ b1,
    const float* __restrict__ w2, const float* __restrict__ b2,
    float* __restrict__ out, int M)
{
    __shared__ __align__(16) float w1s[128 * 16];
    __shared__ __align__(16) float b1s[16];
    __shared__ __align__(16) float w2s[16];
    __shared__ float b2s;

    const int tid = threadIdx.x;
    const int li  = tid & 31;
    const int wid = tid >> 5;

    for (int i = tid; i < 128 * 16; i += LPB) w1s[i] = w1[i];
    if (tid < 16) { b1s[tid] = b1[tid]; w2s[tid] = w2[tid]; }
    if (tid == 0) b2s = b2[0];
    __syncthreads();

    const int lane0 = blockIdx.x * LPB + tid;
    const int lane  = (lane0 < M) ? lane0 : (M - 1);   // clamp: OOB dup last row

    // ---- MLP (packed f32x2 accumulators) ----
    unsigned long long hp[8];
#pragma unroll
    for (int q = 0; q < 8; q++)
        hp[q] = reinterpret_cast<const unsigned long long*>(b1s)[q];

#pragma unroll
    for (int half = 0; half < 2; half++) {
        const float4* x4 = reinterpret_cast<const float4*>(half ? info : ht)
                         + (size_t)lane * (H / 4);
#pragma unroll
        for (int kk = 0; kk < H / 4; kk++) {
            float4 xv = x4[kk];
            const int kbase = half * H + kk * 4;
#pragma unroll
            for (int c = 0; c < 4; c++) {
                float x = (&xv.x)[c];
                unsigned long long xx;
                asm("mov.b64 %0, {%1, %1};" : "=l"(xx) : "f"(x));
                const unsigned long long* wr =
                    reinterpret_cast<const unsigned long long*>(&w1s[(kbase + c) * 16]);
#pragma unroll
                for (int q = 0; q < 8; q++)
                    asm("fma.rn.f32x2 %0, %1, %2, %0;"
                        : "+l"(hp[q]) : "l"(xx), "l"(wr[q]));
            }
        }
    }
    float sc = b2s;
#pragma unroll
    for (int q = 0; q < 8; q++) {
        float lo, hi;
        asm("mov.b64 {%0, %1}, %2;" : "=f"(lo), "=f"(hi) : "l"(hp[q]));
        sc = fmaf(fmaxf(lo, 0.0f), w2s[2 * q + 0], sc);
        sc = fmaf(fmaxf(hi, 0.0f), w2s[2 * q + 1], sc);
    }

    const int s = seg[lane];
    const float ex = (lane0 < M) ? __expf(sc) : 0.0f;   // scores tiny: no max-shift

    // ---- per-segment sum of ex (sorted ids -> warp-segmented reduce) ----
    {
        float v = ex;
#pragma unroll
        for (int o = 1; o < 32; o <<= 1) {
            float u  = __shfl_down_sync(FULLM, v, o);
            int   s2 = __shfl_down_sync(FULLM, s, o);
            if (li + o < 32 && s2 == s) v += u;
        }
        int sp = __shfl_up_sync(FULLM, s, 1);
        if ((li == 0 || sp != s) && v != 0.0f)
            atomicAdd(&g_seg_sum[s], v);
    }

    // ---- warp-local pooling of this warp's 32 lanes ----
    // thread li owns column pair (2li, 2li+1) of each of the 3 arrays.
    const int wbase = blockIdx.x * LPB + wid * 32;
    const float2* hta = reinterpret_cast<const float2*>(ht)  + li;
    const float2* ina = reinterpret_cast<const float2*>(info) + li;
    const float2* fta = reinterpret_cast<const float2*>(fut)  + li;

    const int sp1 = __shfl_up_sync(FULLM, s, 1);
    unsigned bmask = __ballot_sync(FULLM, li > 0 && sp1 != s);
    const bool full_warp = (wbase + 32 <= M);

    float a0 = 0.f, a1 = 0.f, a2 = 0.f, a3 = 0.f, a4 = 0.f, a5 = 0.f;

    if (bmask == 0 && full_warp) {
        // fast path: one segment covers the whole warp
#pragma unroll
        for (int r = 0; r < 32; r += 4) {
            size_t g0 = (size_t)(wbase + r) * (H / 2);
            float2 h0 = hta[g0], h1 = hta[g0 + 32], h2 = hta[g0 + 64], h3 = hta[g0 + 96];
            float2 i0 = ina[g0], i1 = ina[g0 + 32], i2 = ina[g0 + 64], i3 = ina[g0 + 96];
            float2 f0 = fta[g0], f1 = fta[g0 + 32], f2 = fta[g0 + 64], f3 = fta[g0 + 96];
            float p0 = __shfl_sync(FULLM, ex, r + 0);
            float p1 = __shfl_sync(FULLM, ex, r + 1);
            float p2 = __shfl_sync(FULLM, ex, r + 2);
            float p3 = __shfl_sync(FULLM, ex, r + 3);
            a0 = fmaf(p0, h0.x, a0); a1 = fmaf(p0, h0.y, a1);
            a2 = fmaf(p0, i0.x, a2); a3 = fmaf(p0, i0.y, a3);
            a4 = fmaf(p0, f0.x, a4); a5 = fmaf(p0, f0.y, a5);
            a0 = fmaf(p1, h1.x, a0); a1 = fmaf(p1, h1.y, a1);
            a2 = fmaf(p1, i1.x, a2); a3 = fmaf(p1, i1.y, a3);
            a4 = fmaf(p1, f1.x, a4); a5 = fmaf(p1, f1.y, a5);
            a0 = fmaf(p2, h2.x, a0); a1 = fmaf(p2, h2.y, a1);
            a2 = fmaf(p2, i2.x, a2); a3 = fmaf(p2, i2.y, a3);
            a4 = fmaf(p2, f2.x, a4); a5 = fmaf(p2, f2.y, a5);
            a0 = fmaf(p3, h3.x, a0); a1 = fmaf(p3, h3.y, a1);
            a2 = fmaf(p3, i3.x, a2); a3 = fmaf(p3, i3.y, a3);
            a4 = fmaf(p3, f3.x, a4); a5 = fmaf(p3, f3.y, a5);
        }
        const int s0 = __shfl_sync(FULLM, s, 0);
        float* ob = &out[s0 * PCOLS + 2 * li];
        atomicAdd(ob,       a0); atomicAdd(ob + 1,   a1);
        atomicAdd(ob + 64,  a2); atomicAdd(ob + 65,  a3);
        atomicAdd(ob + 128, a4); atomicAdd(ob + 129, a5);
    } else {
        // slow path: segment boundary inside warp and/or partial tail warp
        int cur = __shfl_sync(FULLM, s, 0);
        for (int r = 0; r < 32; r++) {
            int gr = wbase + r;
            if (gr >= M) break;                       // uniform across warp
            int   sr = __shfl_sync(FULLM, s,  r);
            float p  = __shfl_sync(FULLM, ex, r);
            if (sr != cur) {
                float* ob = &out[cur * PCOLS + 2 * li];
                atomicAdd(ob,       a0); atomicAdd(ob + 1,   a1);
                atomicAdd(ob + 64,  a2); atomicAdd(ob + 65,  a3);
                atomicAdd(ob + 128, a4); atomicAdd(ob + 129, a5);
                a0 = a1 = a2 = a3 = a4 = a5 = 0.f;
                cur = sr;
            }
            size_t g0 = (size_t)gr * (H / 2);
            float2 h = hta[g0], iv = ina[g0], f = fta[g0];
            a0 = fmaf(p, h.x,  a0); a1 = fmaf(p, h.y,  a1);
            a2 = fmaf(p, iv.x, a2); a3 = fmaf(p, iv.y, a3);
            a4 = fmaf(p, f.x,  a4); a5 = fmaf(p, f.y,  a5);
        }
        float* ob = &out[cur * PCOLS + 2 * li];
        atomicAdd(ob,       a0); atomicAdd(ob + 1,   a1);
        atomicAdd(ob + 64,  a2); atomicAdd(ob + 65,  a3);
        atomicAdd(ob + 128, a4); atomicAdd(ob + 129, a5);
    }
}

// ---------------- kernel 2: normalize out by seg_sum ----------------
__global__ void normalize_kernel(float* __restrict__ out) {
    int i = blockIdx.x * blockDim.x + threadIdx.x;
    if (i < NSEG * PCOLS)
        out[i] /= g_seg_sum[i / PCOLS];
}

// ---------------- launch ----------------
extern "C" void kernel_launch(void* const* d_in, const int* in_sizes, int n_in,
                              void* d_out, int out_size)
{
    const float* ht   = (const float*)d_in[0];
    const float* info = (const float*)d_in[1];
    const float* fut  = (const float*)d_in[2];
    const int*   seg  = (const int*)  d_in[3];
    const float* w1   = (const float*)d_in[4];
    const float* b1   = (const float*)d_in[5];
    const float* w2   = (const float*)d_in[6];
    const float* b2   = (const float*)d_in[7];
    float* out = (float*)d_out;

    int M = in_sizes[0] / H;

    int init_n = out_size > NSEG ? out_size : NSEG;
    init_kernel<<<(init_n + 255) / 256, 256>>>(out, out_size);

    mega_kernel<<<(M + LPB - 1) / LPB, LPB>>>(ht, info, fut, seg,
                                              w1, b1, w2, b2, out, M);

    normalize_kernel<<<(NSEG * PCOLS + 255) / 256, 256>>>(out);
}